// round 15
// baseline (speedup 1.0000x reference)
#include <cuda_runtime.h>
#include <cuda_fp16.h>
#include <cstdint>

#define SEQ    2048
#define DMODEL 1024
#define NHEAD  16
#define DVDIM  64
#define NBATCH 4
#define MROWS  (NBATCH * SEQ)   // 8192
#define MWORDS (SEQ / 32)
#define LOG2E  1.4426950408889634f

// ---------------- scratch (device globals) ----------------------------------
__device__ __align__(16) __half g_qsh[MROWS * DMODEL];
__device__ __align__(16) __half g_ksh[MROWS * DMODEL];
__device__ __align__(16) __half g_vsh[MROWS * DMODEL];
__device__ __align__(16) __half g_qhi[MROWS * DMODEL];
__device__ __align__(16) __half g_khi[MROWS * DMODEL];
__device__ __align__(16) __half g_vhi[MROWS * DMODEL];
__device__ __align__(16) __half g_chi[MROWS * DMODEL];
__device__ __align__(16) __half g_w16[4 * DMODEL * DMODEL];
__device__ unsigned g_mbits[SEQ * MWORDS];

// ---------------- PTX helpers (sm_103-safe) ---------------------------------
__device__ __forceinline__ uint32_t smem_u32(const void* p) {
    uint32_t a;
    asm("{ .reg .u64 t; cvta.to.shared.u64 t, %1; cvt.u32.u64 %0, t; }" : "=r"(a) : "l"(p));
    return a;
}
#define CP_ASYNC16(dst, src) \
    asm volatile("cp.async.ca.shared.global [%0], [%1], 16;" :: "r"(dst), "l"(src))
#define CP_COMMIT() asm volatile("cp.async.commit_group;" ::: "memory")
#define CP_WAIT(n)  asm volatile("cp.async.wait_group %0;" :: "n"(n) : "memory")
#define STG_CS16(addr, v) \
    asm volatile("st.global.cs.v4.b32 [%0], {%1,%2,%3,%4};" \
                 :: "l"(addr), "r"((v).x), "r"((v).y), "r"((v).z), "r"((v).w) : "memory")

__device__ __forceinline__ void ldsm4(uint32_t* r, uint32_t addr) {
    asm volatile("ldmatrix.sync.aligned.m8n8.x4.shared.b16 {%0,%1,%2,%3}, [%4];"
                 : "=r"(r[0]), "=r"(r[1]), "=r"(r[2]), "=r"(r[3]) : "r"(addr));
}
__device__ __forceinline__ void ldsm4t(uint32_t* r, uint32_t addr) {
    asm volatile("ldmatrix.sync.aligned.m8n8.x4.trans.shared.b16 {%0,%1,%2,%3}, [%4];"
                 : "=r"(r[0]), "=r"(r[1]), "=r"(r[2]), "=r"(r[3]) : "r"(addr));
}
__device__ __forceinline__ void mma_f16(float* d, const uint32_t* a, const uint32_t* b) {
    asm volatile(
        "mma.sync.aligned.m16n8k16.row.col.f32.f16.f16.f32 "
        "{%0,%1,%2,%3}, {%4,%5,%6,%7}, {%8,%9}, {%0,%1,%2,%3};"
        : "+f"(d[0]), "+f"(d[1]), "+f"(d[2]), "+f"(d[3])
        : "r"(a[0]), "r"(a[1]), "r"(a[2]), "r"(a[3]), "r"(b[0]), "r"(b[1]));
}
__device__ __forceinline__ float ex2f(float x) {
    float r; asm("ex2.approx.f32 %0, %1;" : "=f"(r) : "f"(x)); return r;
}
__device__ __forceinline__ uint32_t packh2(float lo, float hi) {
    uint32_t d; asm("cvt.rn.f16x2.f32 %0, %1, %2;" : "=r"(d) : "f"(hi), "f"(lo)); return d;
}

// ---------------- fused prep (flat 1D grid, zero empty blocks) ---------------
// blocks [0,2048)   q act      [2048,4096) k act    [4096,6144) v act
//        [6144,6400) wq        [6400,6656) wk       [6656,6912) wv
//        [6912,7168) wo        [7168,7680) mask pack (inline detect)
#define NACT16 (MROWS * DMODEL / 16)   // 524288 (2048 blocks x 256)
#define NW16   (DMODEL * DMODEL / 16)  // 65536  (256 blocks x 256)
#define NMASKW (SEQ * MWORDS)          // 131072 (512 blocks x 256)
#define PREP_BLOCKS (3 * 2048 + 4 * 256 + 512)   // 7680

__global__ void __launch_bounds__(256) prep_all(
    const float4* __restrict__ q, const float4* __restrict__ k,
    const float4* __restrict__ v,
    const float4* __restrict__ wq, const float4* __restrict__ wk,
    const float4* __restrict__ wv, const float4* __restrict__ wo,
    const void* __restrict__ mask,
    __half* __restrict__ qh, __half* __restrict__ kh,
    __half* __restrict__ vh, __half* __restrict__ w16)
{
    int blk = blockIdx.x;

    if (blk >= 7168) {
        // ---- mask pack with inline per-block dtype detection ----
        int widx = (blk - 7168) * 256 + threadIdx.x;
        __shared__ int f[4];
        int t = threadIdx.x;
        if (t < 4) f[t] = 0;
        __syncthreads();
        const unsigned* m = (const unsigned*)mask;
        int fu8 = 0, ff16 = 0, fbf16 = 0, ff32 = 0;
        for (int s = t; s < 4096; s += 256) {
            unsigned w = m[s];
            if (w == 0x3F800000u) ff32 = 1;
            if (w == 0x3F803F80u || w == 0x00003F80u) fbf16 = 1;
            if (w == 0x3C003C00u || w == 0x00003C00u || w == 0x3C000000u) ff16 = 1;
            if ((w & 0xFEFEFEFEu) == 0u && w > 1u) fu8 = 1;
        }
        if (fu8)  atomicOr(&f[0], 1);
        if (ff16) atomicOr(&f[1], 1);
        if (fbf16) atomicOr(&f[2], 1);
        if (ff32) atomicOr(&f[3], 1);
        __syncthreads();
        int mode;
        if (f[1]) mode = 4;
        else if (f[2]) mode = 3;
        else if (f[3]) mode = 2;
        else if (f[0]) mode = 1;
        else mode = 0;

        long base = (long)widx * 32;
        unsigned bits = 0;
        if (mode == 0) {
            const int* p = (const int*)mask;
            #pragma unroll 8
            for (int j = 0; j < 32; j++) if (p[base + j] != 0) bits |= 1u << j;
        } else if (mode == 1) {
            const unsigned char* p = (const unsigned char*)mask;
            #pragma unroll 8
            for (int j = 0; j < 32; j++) if (p[base + j] != 0) bits |= 1u << j;
        } else if (mode == 2) {
            const float* p = (const float*)mask;
            #pragma unroll 8
            for (int j = 0; j < 32; j++) if (p[base + j] != 0.0f) bits |= 1u << j;
        } else {
            const unsigned short* p = (const unsigned short*)mask;
            #pragma unroll 8
            for (int j = 0; j < 32; j++) if (p[base + j] != 0) bits |= 1u << j;
        }
        g_mbits[widx] = bits;
        return;
    }

    const float4* src;
    __half* dst;
    int i;
    if (blk < 6144) {
        int z = blk >> 11;                 // 0,1,2
        i = (blk & 2047) * 256 + threadIdx.x;
        src = (z == 0) ? q : (z == 1) ? k : v;
        dst = (z == 0) ? qh : (z == 1) ? kh : vh;
    } else {
        int w = (blk - 6144) >> 8;         // 0..3
        i = ((blk - 6144) & 255) * 256 + threadIdx.x;
        src = (w == 0) ? wq : (w == 1) ? wk : (w == 2) ? wv : wo;
        dst = w16 + (size_t)w * DMODEL * DMODEL;
    }
    float4 a = src[4 * i], b = src[4 * i + 1];
    float4 c = src[4 * i + 2], d = src[4 * i + 3];
    uint4 o0, o1;
    o0.x = packh2(a.x, a.y); o0.y = packh2(a.z, a.w);
    o0.z = packh2(b.x, b.y); o0.w = packh2(b.z, b.w);
    o1.x = packh2(c.x, c.y); o1.y = packh2(c.z, c.w);
    o1.z = packh2(d.x, d.y); o1.w = packh2(d.z, d.w);
    uint4* op = (uint4*)dst + 2 * i;
    STG_CS16(op, o0);
    STG_CS16(op + 1, o1);
}

// ---------------- mma.sync fp16 GEMM (at HMMA floor) --------------------------
#define LDA_B   80
#define TILE_B  10240
#define STAGE_B 20480
#define NITER   (DMODEL / 32)

struct Job {
    const __half* A1; const __half* B1;
    const float* bias;
    float* Yf; __half* H1;
    int mode; float scale;
};
struct Jobs3 { Job j[3]; };

__global__ void __launch_bounds__(128) gemm_mma(Jobs3 jobs)
{
    extern __shared__ char sm[];
    uint32_t smb = smem_u32(sm);
    Job jb = jobs.j[blockIdx.z];
    int tid = threadIdx.x, lane = tid & 31, wid = tid >> 5;
    int wm = wid >> 1, wn = wid & 1;
    int m0 = blockIdx.y * 128, n0 = blockIdx.x * 128;

    float acc[4][8][4];
    #pragma unroll
    for (int i = 0; i < 4; i++)
        #pragma unroll
        for (int j = 0; j < 8; j++)
            #pragma unroll
            for (int q = 0; q < 4; q++) acc[i][j][q] = 0.0f;

    const __half* A1p = jb.A1; const __half* B1p = jb.B1;

    auto issue = [&](int t) {
        uint32_t st = smb + (t % 3) * STAGE_B;
        int k0 = t * 32;
        #pragma unroll
        for (int i = 0; i < 4; i++) {
            int idx = tid + i * 128;
            int r = idx >> 2, c = idx & 3;
            uint32_t d = st + r * LDA_B + c * 16;
            size_t ga = (size_t)(m0 + r) * DMODEL + k0 + c * 8;
            size_t gb = (size_t)(n0 + r) * DMODEL + k0 + c * 8;
            CP_ASYNC16(d,          A1p + ga);
            CP_ASYNC16(d + TILE_B, B1p + gb);
        }
        CP_COMMIT();
    };
    issue(0);
    issue(1);

    for (int t = 0; t < NITER; t++) {
        if (t + 1 < NITER) { CP_WAIT(1); } else { CP_WAIT(0); }
        __syncthreads();
        if (t + 2 < NITER) issue(t + 2);

        uint32_t st = smb + (t % 3) * STAGE_B;
        uint32_t aA = st + (wm * 64 + (lane & 15)) * LDA_B + (lane >> 4) * 16;
        uint32_t aB = st + TILE_B + (wn * 64 + (lane & 7)) * LDA_B + (lane >> 3) * 16;

        uint32_t bh[8][4];
        #pragma unroll
        for (int ni = 0; ni < 8; ni++) ldsm4(bh[ni], aB + ni * 8 * LDA_B);

        #pragma unroll
        for (int ks = 0; ks < 2; ks++) {
            uint32_t ah[4][4];
            #pragma unroll
            for (int mi = 0; mi < 4; mi++)
                ldsm4(ah[mi], aA + mi * 16 * LDA_B + ks * 32);
            #pragma unroll
            for (int mi = 0; mi < 4; mi++)
                #pragma unroll
                for (int ni = 0; ni < 8; ni++)
                    mma_f16(acc[mi][ni], ah[mi], &bh[ni][2 * ks]);
        }
    }

    int er = lane >> 2, ec = (lane & 3) * 2;
    #pragma unroll
    for (int mi = 0; mi < 4; mi++) {
        #pragma unroll
        for (int ni = 0; ni < 8; ni++) {
            int row = m0 + wm * 64 + mi * 16 + er;
            int col = n0 + wn * 64 + ni * 8 + ec;
            float b0 = jb.bias[col], b1 = jb.bias[col + 1];
            float x00 = acc[mi][ni][0] + b0, x01 = acc[mi][ni][1] + b1;
            float x10 = acc[mi][ni][2] + b0, x11 = acc[mi][ni][3] + b1;
            if (jb.mode == 0) {
                *(float2*)(jb.Yf + (size_t)row * DMODEL + col) = float2{x00, x01};
                *(float2*)(jb.Yf + (size_t)(row + 8) * DMODEL + col) = float2{x10, x11};
            } else {
                x00 *= jb.scale; x01 *= jb.scale; x10 *= jb.scale; x11 *= jb.scale;
                *(__half2*)(jb.H1 + (size_t)row * DMODEL + col) =
                    __half2{__float2half_rn(x00), __float2half_rn(x01)};
                *(__half2*)(jb.H1 + (size_t)(row + 8) * DMODEL + col) =
                    __half2{__float2half_rn(x10), __float2half_rn(x11)};
            }
        }
    }
}

// ---------------- fused MMA flash attention (R11/R13 version) -----------------
#define FSTR 72
#define MASKVAL 1.4426950409e-9f
#define KVSTG 4608
#define NT (SEQ / 64)

__global__ void __launch_bounds__(256, 2) flash_mma(
    const __half* __restrict__ qhi, const __half* __restrict__ khi,
    const __half* __restrict__ vhi, __half* __restrict__ chi)
{
    extern __shared__ __half sh[];
    const int O_QHI = 0;
    const int O_KH0 = 9216;
    const int O_V0  = 9216 + 3 * KVSTG;
    uint32_t sb = smem_u32(sh);

    int tid = threadIdx.x, lane = tid & 31, wm = tid >> 5;
    int q0 = blockIdx.x * 128, h = blockIdx.y, b = blockIdx.z;
    size_t rowbase = (size_t)b * SEQ;
    int r4 = lane >> 2, c2 = lane & 3;

    {
        const __half* qh = qhi + (rowbase + q0) * DMODEL + h * 64;
        #pragma unroll
        for (int c = tid; c < 1024; c += 256) {
            int r = c >> 3, dc = c & 7;
            CP_ASYNC16(sb + (O_QHI + r * FSTR + dc * 8) * 2, qh + (size_t)r * DMODEL + dc * 8);
        }
        CP_COMMIT();
    }
    const __half* kbh = khi + rowbase * DMODEL + h * 64;
    const __half* vb  = vhi + rowbase * DMODEL + h * 64;

    auto issue_kv = [&](int t) {
        int st = t % 3;
        int k0 = t * 64;
        #pragma unroll
        for (int c = tid; c < 512; c += 256) {
            int r = c >> 3, dc = c & 7;
            size_t g = (size_t)(k0 + r) * DMODEL + dc * 8;
            CP_ASYNC16(sb + (O_KH0 + st * KVSTG + r * FSTR + dc * 8) * 2, kbh + g);
            CP_ASYNC16(sb + (O_V0  + st * KVSTG + r * FSTR + dc * 8) * 2, vb + g);
        }
        CP_COMMIT();
    };
    issue_kv(0);
    issue_kv(1);

    float O[8][4];
    #pragma unroll
    for (int ni = 0; ni < 8; ni++)
        #pragma unroll
        for (int q = 0; q < 4; q++) O[ni][q] = 0.0f;
    float lsum[2] = {0.f, 0.f};
    float mrow[2] = {-1e30f, -1e30f};

    for (int t = 0; t < NT; t++) {
        if (t + 2 < NT) { CP_WAIT(1); } else { CP_WAIT(0); }
        __syncthreads();
        if (t + 2 < NT) issue_kv(t + 2);

        int st = t % 3;
        uint32_t kbase = sb + (O_KH0 + st * KVSTG) * 2;
        uint32_t vbase = sb + (O_V0  + st * KVSTG) * 2;

        uint2 mw[2];
        #pragma unroll
        for (int rr = 0; rr < 2; rr++) {
            int grow = q0 + wm * 16 + r4 + rr * 8;
            mw[rr] = __ldg((const uint2*)&g_mbits[(size_t)grow * MWORDS + 2 * t]);
        }

        float S[8][4];
        #pragma unroll
        for (int ni = 0; ni < 8; ni++)
            #pragma unroll
            for (int q = 0; q < 4; q++) S[ni][q] = 0.0f;

        #pragma unroll
        for (int ks = 0; ks < 4; ks++) {
            uint32_t aH[4];
            {
                uint32_t abase = sb + (((wm * 16 + (lane & 15)) * FSTR) +
                                       (lane >> 4) * 8 + ks * 16) * 2;
                ldsm4(aH, abase);
            }
            uint32_t bH[8][2];
            #pragma unroll
            for (int np = 0; np < 4; np++) {
                uint32_t r4v[4];
                uint32_t boff = ((np * 16 + (lane & 7) + ((lane >> 4) & 1) * 8) * FSTR +
                                 ks * 16 + ((lane >> 3) & 1) * 8) * 2;
                ldsm4(r4v, kbase + boff);
                bH[2 * np][0] = r4v[0];     bH[2 * np][1] = r4v[1];
                bH[2 * np + 1][0] = r4v[2]; bH[2 * np + 1][1] = r4v[3];
            }
            #pragma unroll
            for (int ni = 0; ni < 8; ni++)
                mma_f16(S[ni], aH, bH[ni]);
        }

        float mnew[2] = {mrow[0], mrow[1]};
        #pragma unroll
        for (int ni = 0; ni < 8; ni++) {
            uint32_t w0 = (ni < 4) ? mw[0].x : mw[0].y;
            uint32_t w1 = (ni < 4) ? mw[1].x : mw[1].y;
            int shf = (ni & 3) * 8 + 2 * c2;
            if ((w0 >> shf) & 1u)       S[ni][0] = MASKVAL;
            if ((w0 >> (shf + 1)) & 1u) S[ni][1] = MASKVAL;
            if ((w1 >> shf) & 1u)       S[ni][2] = MASKVAL;
            if ((w1 >> (shf + 1)) & 1u) S[ni][3] = MASKVAL;
            mnew[0] = fmaxf(mnew[0], fmaxf(S[ni][0], S[ni][1]));
            mnew[1] = fmaxf(mnew[1], fmaxf(S[ni][2], S[ni][3]));
        }
        #pragma unroll
        for (int j = 0; j < 2; j++) {
            mnew[j] = fmaxf(mnew[j], __shfl_xor_sync(0xffffffffu, mnew[j], 1));
            mnew[j] = fmaxf(mnew[j], __shfl_xor_sync(0xffffffffu, mnew[j], 2));
        }
        float al[2];
        #pragma unroll
        for (int j = 0; j < 2; j++) {
            al[j] = ex2f(mrow[j] - mnew[j]);
            mrow[j] = mnew[j];
            lsum[j] *= al[j];
        }
        #pragma unroll
        for (int ni = 0; ni < 8; ni++) {
            O[ni][0] *= al[0]; O[ni][1] *= al[0];
            O[ni][2] *= al[1]; O[ni][3] *= al[1];
        }

        uint32_t pa[4][4];
        #pragma unroll
        for (int ni = 0; ni < 8; ni++) {
            float p0 = ex2f(S[ni][0] - mnew[0]);
            float p1 = ex2f(S[ni][1] - mnew[0]);
            float p2 = ex2f(S[ni][2] - mnew[1]);
            float p3 = ex2f(S[ni][3] - mnew[1]);
            lsum[0] += p0 + p1;
            lsum[1] += p2 + p3;
            int ks = ni >> 1, half = ni & 1;
            pa[ks][half * 2 + 0] = packh2(p0, p1);
            pa[ks][half * 2 + 1] = packh2(p2, p3);
        }

        #pragma unroll
        for (int ks = 0; ks < 4; ks++) {
            #pragma unroll
            for (int nn = 0; nn < 4; nn++) {
                uint32_t vb4[4];
                int key = ks * 16 + (lane & 7) + ((lane >> 3) & 1) * 8;
                int dim = nn * 16 + ((lane >> 4) & 1) * 8;
                ldsm4t(vb4, vbase + (key * FSTR + dim) * 2);
                mma_f16(O[2 * nn],     pa[ks], &vb4[0]);
                mma_f16(O[2 * nn + 1], pa[ks], &vb4[2]);
            }
        }
    }

    #pragma unroll
    for (int j = 0; j < 2; j++) {
        lsum[j] += __shfl_xor_sync(0xffffffffu, lsum[j], 1);
        lsum[j] += __shfl_xor_sync(0xffffffffu, lsum[j], 2);
        lsum[j] = 1.0f / lsum[j];
    }
    #pragma unroll
    for (int ni = 0; ni < 8; ni++) {
        size_t grow = rowbase + q0 + wm * 16 + r4;
        int col = h * 64 + ni * 8 + 2 * c2;
        float x00 = O[ni][0] * lsum[0];
        float x01 = O[ni][1] * lsum[0];
        float x10 = O[ni][2] * lsum[1];
        float x11 = O[ni][3] * lsum[1];
        *(__half2*)(chi + grow * DMODEL + col) =
            __half2{__float2half_rn(x00), __float2half_rn(x01)};
        *(__half2*)(chi + (grow + 8) * DMODEL + col) =
            __half2{__float2half_rn(x10), __float2half_rn(x11)};
    }
}

// ---------------- launch ------------------------------------------------------
extern "C" void kernel_launch(void* const* d_in, const int* in_sizes, int n_in,
                              void* d_out, int out_size)
{
    const float* q    = (const float*)d_in[0];
    const float* k    = (const float*)d_in[1];
    const float* v    = (const float*)d_in[2];
    const void*  mask = d_in[3];
    const float* Wq   = (const float*)d_in[4];
    const float* bq   = (const float*)d_in[5];
    const float* Wk   = (const float*)d_in[6];
    const float* bk   = (const float*)d_in[7];
    const float* Wv   = (const float*)d_in[8];
    const float* bv   = (const float*)d_in[9];
    const float* Wo   = (const float*)d_in[10];
    const float* bo   = (const float*)d_in[11];

    __half *qsh, *ksh, *vsh, *qhi, *khi, *vhi, *chi, *w16;
    cudaGetSymbolAddress((void**)&qsh, g_qsh);
    cudaGetSymbolAddress((void**)&ksh, g_ksh);
    cudaGetSymbolAddress((void**)&vsh, g_vsh);
    cudaGetSymbolAddress((void**)&qhi, g_qhi);
    cudaGetSymbolAddress((void**)&khi, g_khi);
    cudaGetSymbolAddress((void**)&vhi, g_vhi);
    cudaGetSymbolAddress((void**)&chi, g_chi);
    cudaGetSymbolAddress((void**)&w16, g_w16);

    const int gemm_smem = 3 * STAGE_B;              // 61440
    const int flash_smem = (9216 + 6 * KVSTG) * 2;  // 73728
    static bool attr_set = false;
    if (!attr_set) {
        cudaFuncSetAttribute(gemm_mma, cudaFuncAttributeMaxDynamicSharedMemorySize, gemm_smem);
        cudaFuncSetAttribute(flash_mma, cudaFuncAttributeMaxDynamicSharedMemorySize, flash_smem);
        attr_set = true;
    }

    const float qscale = 0.125f * LOG2E;

    // single prep launch, exact-sized flat grid (no empty blocks)
    prep_all<<<PREP_BLOCKS, 256>>>(
        (const float4*)q, (const float4*)k, (const float4*)v,
        (const float4*)Wq, (const float4*)Wk, (const float4*)Wv, (const float4*)Wo,
        mask, qsh, ksh, vsh, w16);

    Jobs3 pj;
    pj.j[0] = Job{qsh, w16,                     bq, nullptr, qhi, 2, qscale};
    pj.j[1] = Job{ksh, w16 + 1 * DMODEL*DMODEL, bk, nullptr, khi, 2, 1.0f};
    pj.j[2] = Job{vsh, w16 + 2 * DMODEL*DMODEL, bv, nullptr, vhi, 2, 1.0f};
    gemm_mma<<<dim3(8, 64, 3), 128, gemm_smem>>>(pj);

    flash_mma<<<dim3(SEQ / 128, NHEAD, NBATCH), 256, flash_smem>>>(qhi, khi, vhi, chi);

    Jobs3 oj;
    oj.j[0] = Job{chi, w16 + 3 * DMODEL*DMODEL, bo, (float*)d_out, nullptr, 0, 1.0f};
    oj.j[1] = oj.j[0];
    oj.j[2] = oj.j[0];
    gemm_mma<<<dim3(8, 64, 1), 128, gemm_smem>>>(oj);
}

// round 16
// speedup vs baseline: 1.0151x; 1.0151x over previous
#include <cuda_runtime.h>
#include <cuda_fp16.h>
#include <cstdint>

#define SEQ    2048
#define DMODEL 1024
#define NHEAD  16
#define DVDIM  64
#define NBATCH 4
#define MROWS  (NBATCH * SEQ)   // 8192
#define MWORDS (SEQ / 32)
#define LOG2E  1.4426950408889634f

// ---------------- scratch (device globals) ----------------------------------
__device__ __align__(16) __half g_qsh[MROWS * DMODEL];
__device__ __align__(16) __half g_ksh[MROWS * DMODEL];
__device__ __align__(16) __half g_vsh[MROWS * DMODEL];
__device__ __align__(16) __half g_qhi[MROWS * DMODEL];
__device__ __align__(16) __half g_khi[MROWS * DMODEL];
__device__ __align__(16) __half g_vhi[MROWS * DMODEL];
__device__ __align__(16) __half g_chi[MROWS * DMODEL];
__device__ __align__(16) __half g_w16[4 * DMODEL * DMODEL];
__device__ unsigned g_mbits[SEQ * MWORDS];
__device__ int g_mode;

// ---------------- PTX helpers (sm_103-safe) ---------------------------------
__device__ __forceinline__ uint32_t smem_u32(const void* p) {
    uint32_t a;
    asm("{ .reg .u64 t; cvta.to.shared.u64 t, %1; cvt.u32.u64 %0, t; }" : "=r"(a) : "l"(p));
    return a;
}
#define CP_ASYNC16(dst, src) \
    asm volatile("cp.async.ca.shared.global [%0], [%1], 16;" :: "r"(dst), "l"(src))
#define CP_COMMIT() asm volatile("cp.async.commit_group;" ::: "memory")
#define CP_WAIT(n)  asm volatile("cp.async.wait_group %0;" :: "n"(n) : "memory")
#define STG_CS16(addr, v) \
    asm volatile("st.global.cs.v4.b32 [%0], {%1,%2,%3,%4};" \
                 :: "l"(addr), "r"((v).x), "r"((v).y), "r"((v).z), "r"((v).w) : "memory")

__device__ __forceinline__ void ldsm4(uint32_t* r, uint32_t addr) {
    asm volatile("ldmatrix.sync.aligned.m8n8.x4.shared.b16 {%0,%1,%2,%3}, [%4];"
                 : "=r"(r[0]), "=r"(r[1]), "=r"(r[2]), "=r"(r[3]) : "r"(addr));
}
__device__ __forceinline__ void ldsm4t(uint32_t* r, uint32_t addr) {
    asm volatile("ldmatrix.sync.aligned.m8n8.x4.trans.shared.b16 {%0,%1,%2,%3}, [%4];"
                 : "=r"(r[0]), "=r"(r[1]), "=r"(r[2]), "=r"(r[3]) : "r"(addr));
}
__device__ __forceinline__ void mma_f16(float* d, const uint32_t* a, const uint32_t* b) {
    asm volatile(
        "mma.sync.aligned.m16n8k16.row.col.f32.f16.f16.f32 "
        "{%0,%1,%2,%3}, {%4,%5,%6,%7}, {%8,%9}, {%0,%1,%2,%3};"
        : "+f"(d[0]), "+f"(d[1]), "+f"(d[2]), "+f"(d[3])
        : "r"(a[0]), "r"(a[1]), "r"(a[2]), "r"(a[3]), "r"(b[0]), "r"(b[1]));
}
__device__ __forceinline__ float ex2f(float x) {
    float r; asm("ex2.approx.f32 %0, %1;" : "=f"(r) : "f"(x)); return r;
}
__device__ __forceinline__ uint32_t packh2(float lo, float hi) {
    uint32_t d; asm("cvt.rn.f16x2.f32 %0, %1, %2;" : "=r"(d) : "f"(hi), "f"(lo)); return d;
}

// ---------------- mask handling (separate kernels — R13 proven) --------------
__global__ void detect_mask(const unsigned* __restrict__ m) {
    __shared__ int f[4];
    int t = threadIdx.x;
    if (t < 4) f[t] = 0;
    __syncthreads();
    int fu8 = 0, ff16 = 0, fbf16 = 0, ff32 = 0;
    for (int i = t; i < 4096; i += 256) {
        unsigned w = m[i];
        if (w == 0x3F800000u) ff32 = 1;
        if (w == 0x3F803F80u || w == 0x00003F80u) fbf16 = 1;
        if (w == 0x3C003C00u || w == 0x00003C00u || w == 0x3C000000u) ff16 = 1;
        if ((w & 0xFEFEFEFEu) == 0u && w > 1u) fu8 = 1;
    }
    if (fu8)  atomicOr(&f[0], 1);
    if (ff16) atomicOr(&f[1], 1);
    if (fbf16) atomicOr(&f[2], 1);
    if (ff32) atomicOr(&f[3], 1);
    __syncthreads();
    if (t == 0) {
        int mode;
        if (f[1]) mode = 4;
        else if (f[2]) mode = 3;
        else if (f[3]) mode = 2;
        else if (f[0]) mode = 1;
        else mode = 0;
        g_mode = mode;
    }
}

__global__ void pack_mask(const void* __restrict__ mp) {
    int idx = blockIdx.x * blockDim.x + threadIdx.x;
    int mode = g_mode;
    long base = (long)idx * 32;
    unsigned bits = 0;
    if (mode == 0) {
        const int* p = (const int*)mp;
        #pragma unroll 8
        for (int j = 0; j < 32; j++) if (p[base + j] != 0) bits |= 1u << j;
    } else if (mode == 1) {
        const unsigned char* p = (const unsigned char*)mp;
        #pragma unroll 8
        for (int j = 0; j < 32; j++) if (p[base + j] != 0) bits |= 1u << j;
    } else if (mode == 2) {
        const float* p = (const float*)mp;
        #pragma unroll 8
        for (int j = 0; j < 32; j++) if (p[base + j] != 0.0f) bits |= 1u << j;
    } else {
        const unsigned short* p = (const unsigned short*)mp;
        #pragma unroll 8
        for (int j = 0; j < 32; j++) if (p[base + j] != 0) bits |= 1u << j;
    }
    g_mbits[idx] = bits;
}

// ---------------- prep: conversions, flat exact grid (no empty blocks) -------
// blocks [0,2048) q | [2048,4096) k | [4096,6144) v |
//        [6144,6400) wq | [6400,6656) wk | [6656,6912) wv | [6912,7168) wo
#define CONV_BLOCKS 7168

__global__ void __launch_bounds__(256) conv_all(
    const float4* __restrict__ q, const float4* __restrict__ k,
    const float4* __restrict__ v,
    const float4* __restrict__ wq, const float4* __restrict__ wk,
    const float4* __restrict__ wv, const float4* __restrict__ wo,
    __half* __restrict__ qh, __half* __restrict__ kh,
    __half* __restrict__ vh, __half* __restrict__ w16)
{
    int blk = blockIdx.x;
    const float4* src;
    __half* dst;
    int i;
    if (blk < 6144) {
        int z = blk >> 11;                 // 0,1,2
        i = (blk & 2047) * 256 + threadIdx.x;
        src = (z == 0) ? q : (z == 1) ? k : v;
        dst = (z == 0) ? qh : (z == 1) ? kh : vh;
    } else {
        int w = (blk - 6144) >> 8;         // 0..3
        i = ((blk - 6144) & 255) * 256 + threadIdx.x;
        src = (w == 0) ? wq : (w == 1) ? wk : (w == 2) ? wv : wo;
        dst = w16 + (size_t)w * DMODEL * DMODEL;
    }
    float4 a = src[4 * i], b = src[4 * i + 1];
    float4 c = src[4 * i + 2], d = src[4 * i + 3];
    uint4 o0, o1;
    o0.x = packh2(a.x, a.y); o0.y = packh2(a.z, a.w);
    o0.z = packh2(b.x, b.y); o0.w = packh2(b.z, b.w);
    o1.x = packh2(c.x, c.y); o1.y = packh2(c.z, c.w);
    o1.z = packh2(d.x, d.y); o1.w = packh2(d.z, d.w);
    uint4* op = (uint4*)dst + 2 * i;
    STG_CS16(op, o0);
    STG_CS16(op + 1, o1);
}

// ---------------- mma.sync fp16 GEMM (at HMMA floor) --------------------------
#define LDA_B   80
#define TILE_B  10240
#define STAGE_B 20480
#define NITER   (DMODEL / 32)

struct Job {
    const __half* A1; const __half* B1;
    const float* bias;
    float* Yf; __half* H1;
    int mode; float scale;
};
struct Jobs3 { Job j[3]; };

__global__ void __launch_bounds__(128) gemm_mma(Jobs3 jobs)
{
    extern __shared__ char sm[];
    uint32_t smb = smem_u32(sm);
    Job jb = jobs.j[blockIdx.z];
    int tid = threadIdx.x, lane = tid & 31, wid = tid >> 5;
    int wm = wid >> 1, wn = wid & 1;
    int m0 = blockIdx.y * 128, n0 = blockIdx.x * 128;

    float acc[4][8][4];
    #pragma unroll
    for (int i = 0; i < 4; i++)
        #pragma unroll
        for (int j = 0; j < 8; j++)
            #pragma unroll
            for (int q = 0; q < 4; q++) acc[i][j][q] = 0.0f;

    const __half* A1p = jb.A1; const __half* B1p = jb.B1;

    auto issue = [&](int t) {
        uint32_t st = smb + (t % 3) * STAGE_B;
        int k0 = t * 32;
        #pragma unroll
        for (int i = 0; i < 4; i++) {
            int idx = tid + i * 128;
            int r = idx >> 2, c = idx & 3;
            uint32_t d = st + r * LDA_B + c * 16;
            size_t ga = (size_t)(m0 + r) * DMODEL + k0 + c * 8;
            size_t gb = (size_t)(n0 + r) * DMODEL + k0 + c * 8;
            CP_ASYNC16(d,          A1p + ga);
            CP_ASYNC16(d + TILE_B, B1p + gb);
        }
        CP_COMMIT();
    };
    issue(0);
    issue(1);

    for (int t = 0; t < NITER; t++) {
        if (t + 1 < NITER) { CP_WAIT(1); } else { CP_WAIT(0); }
        __syncthreads();
        if (t + 2 < NITER) issue(t + 2);

        uint32_t st = smb + (t % 3) * STAGE_B;
        uint32_t aA = st + (wm * 64 + (lane & 15)) * LDA_B + (lane >> 4) * 16;
        uint32_t aB = st + TILE_B + (wn * 64 + (lane & 7)) * LDA_B + (lane >> 3) * 16;

        uint32_t bh[8][4];
        #pragma unroll
        for (int ni = 0; ni < 8; ni++) ldsm4(bh[ni], aB + ni * 8 * LDA_B);

        #pragma unroll
        for (int ks = 0; ks < 2; ks++) {
            uint32_t ah[4][4];
            #pragma unroll
            for (int mi = 0; mi < 4; mi++)
                ldsm4(ah[mi], aA + mi * 16 * LDA_B + ks * 32);
            #pragma unroll
            for (int mi = 0; mi < 4; mi++)
                #pragma unroll
                for (int ni = 0; ni < 8; ni++)
                    mma_f16(acc[mi][ni], ah[mi], &bh[ni][2 * ks]);
        }
    }

    int er = lane >> 2, ec = (lane & 3) * 2;
    #pragma unroll
    for (int mi = 0; mi < 4; mi++) {
        #pragma unroll
        for (int ni = 0; ni < 8; ni++) {
            int row = m0 + wm * 64 + mi * 16 + er;
            int col = n0 + wn * 64 + ni * 8 + ec;
            float b0 = jb.bias[col], b1 = jb.bias[col + 1];
            float x00 = acc[mi][ni][0] + b0, x01 = acc[mi][ni][1] + b1;
            float x10 = acc[mi][ni][2] + b0, x11 = acc[mi][ni][3] + b1;
            if (jb.mode == 0) {
                *(float2*)(jb.Yf + (size_t)row * DMODEL + col) = float2{x00, x01};
                *(float2*)(jb.Yf + (size_t)(row + 8) * DMODEL + col) = float2{x10, x11};
            } else {
                x00 *= jb.scale; x01 *= jb.scale; x10 *= jb.scale; x11 *= jb.scale;
                *(__half2*)(jb.H1 + (size_t)row * DMODEL + col) =
                    __half2{__float2half_rn(x00), __float2half_rn(x01)};
                *(__half2*)(jb.H1 + (size_t)(row + 8) * DMODEL + col) =
                    __half2{__float2half_rn(x10), __float2half_rn(x11)};
            }
        }
    }
}

// ---------------- fused MMA flash attention (R11/R13 version) -----------------
#define FSTR 72
#define MASKVAL 1.4426950409e-9f
#define KVSTG 4608
#define NT (SEQ / 64)

__global__ void __launch_bounds__(256, 2) flash_mma(
    const __half* __restrict__ qhi, const __half* __restrict__ khi,
    const __half* __restrict__ vhi, __half* __restrict__ chi)
{
    extern __shared__ __half sh[];
    const int O_QHI = 0;
    const int O_KH0 = 9216;
    const int O_V0  = 9216 + 3 * KVSTG;
    uint32_t sb = smem_u32(sh);

    int tid = threadIdx.x, lane = tid & 31, wm = tid >> 5;
    int q0 = blockIdx.x * 128, h = blockIdx.y, b = blockIdx.z;
    size_t rowbase = (size_t)b * SEQ;
    int r4 = lane >> 2, c2 = lane & 3;

    {
        const __half* qh = qhi + (rowbase + q0) * DMODEL + h * 64;
        #pragma unroll
        for (int c = tid; c < 1024; c += 256) {
            int r = c >> 3, dc = c & 7;
            CP_ASYNC16(sb + (O_QHI + r * FSTR + dc * 8) * 2, qh + (size_t)r * DMODEL + dc * 8);
        }
        CP_COMMIT();
    }
    const __half* kbh = khi + rowbase * DMODEL + h * 64;
    const __half* vb  = vhi + rowbase * DMODEL + h * 64;

    auto issue_kv = [&](int t) {
        int st = t % 3;
        int k0 = t * 64;
        #pragma unroll
        for (int c = tid; c < 512; c += 256) {
            int r = c >> 3, dc = c & 7;
            size_t g = (size_t)(k0 + r) * DMODEL + dc * 8;
            CP_ASYNC16(sb + (O_KH0 + st * KVSTG + r * FSTR + dc * 8) * 2, kbh + g);
            CP_ASYNC16(sb + (O_V0  + st * KVSTG + r * FSTR + dc * 8) * 2, vb + g);
        }
        CP_COMMIT();
    };
    issue_kv(0);
    issue_kv(1);

    float O[8][4];
    #pragma unroll
    for (int ni = 0; ni < 8; ni++)
        #pragma unroll
        for (int q = 0; q < 4; q++) O[ni][q] = 0.0f;
    float lsum[2] = {0.f, 0.f};
    float mrow[2] = {-1e30f, -1e30f};

    for (int t = 0; t < NT; t++) {
        if (t + 2 < NT) { CP_WAIT(1); } else { CP_WAIT(0); }
        __syncthreads();
        if (t + 2 < NT) issue_kv(t + 2);

        int st = t % 3;
        uint32_t kbase = sb + (O_KH0 + st * KVSTG) * 2;
        uint32_t vbase = sb + (O_V0  + st * KVSTG) * 2;

        uint2 mw[2];
        #pragma unroll
        for (int rr = 0; rr < 2; rr++) {
            int grow = q0 + wm * 16 + r4 + rr * 8;
            mw[rr] = __ldg((const uint2*)&g_mbits[(size_t)grow * MWORDS + 2 * t]);
        }

        float S[8][4];
        #pragma unroll
        for (int ni = 0; ni < 8; ni++)
            #pragma unroll
            for (int q = 0; q < 4; q++) S[ni][q] = 0.0f;

        #pragma unroll
        for (int ks = 0; ks < 4; ks++) {
            uint32_t aH[4];
            {
                uint32_t abase = sb + (((wm * 16 + (lane & 15)) * FSTR) +
                                       (lane >> 4) * 8 + ks * 16) * 2;
                ldsm4(aH, abase);
            }
            uint32_t bH[8][2];
            #pragma unroll
            for (int np = 0; np < 4; np++) {
                uint32_t r4v[4];
                uint32_t boff = ((np * 16 + (lane & 7) + ((lane >> 4) & 1) * 8) * FSTR +
                                 ks * 16 + ((lane >> 3) & 1) * 8) * 2;
                ldsm4(r4v, kbase + boff);
                bH[2 * np][0] = r4v[0];     bH[2 * np][1] = r4v[1];
                bH[2 * np + 1][0] = r4v[2]; bH[2 * np + 1][1] = r4v[3];
            }
            #pragma unroll
            for (int ni = 0; ni < 8; ni++)
                mma_f16(S[ni], aH, bH[ni]);
        }

        float mnew[2] = {mrow[0], mrow[1]};
        #pragma unroll
        for (int ni = 0; ni < 8; ni++) {
            uint32_t w0 = (ni < 4) ? mw[0].x : mw[0].y;
            uint32_t w1 = (ni < 4) ? mw[1].x : mw[1].y;
            int shf = (ni & 3) * 8 + 2 * c2;
            if ((w0 >> shf) & 1u)       S[ni][0] = MASKVAL;
            if ((w0 >> (shf + 1)) & 1u) S[ni][1] = MASKVAL;
            if ((w1 >> shf) & 1u)       S[ni][2] = MASKVAL;
            if ((w1 >> (shf + 1)) & 1u) S[ni][3] = MASKVAL;
            mnew[0] = fmaxf(mnew[0], fmaxf(S[ni][0], S[ni][1]));
            mnew[1] = fmaxf(mnew[1], fmaxf(S[ni][2], S[ni][3]));
        }
        #pragma unroll
        for (int j = 0; j < 2; j++) {
            mnew[j] = fmaxf(mnew[j], __shfl_xor_sync(0xffffffffu, mnew[j], 1));
            mnew[j] = fmaxf(mnew[j], __shfl_xor_sync(0xffffffffu, mnew[j], 2));
        }
        float al[2];
        #pragma unroll
        for (int j = 0; j < 2; j++) {
            al[j] = ex2f(mrow[j] - mnew[j]);
            mrow[j] = mnew[j];
            lsum[j] *= al[j];
        }
        #pragma unroll
        for (int ni = 0; ni < 8; ni++) {
            O[ni][0] *= al[0]; O[ni][1] *= al[0];
            O[ni][2] *= al[1]; O[ni][3] *= al[1];
        }

        uint32_t pa[4][4];
        #pragma unroll
        for (int ni = 0; ni < 8; ni++) {
            float p0 = ex2f(S[ni][0] - mnew[0]);
            float p1 = ex2f(S[ni][1] - mnew[0]);
            float p2 = ex2f(S[ni][2] - mnew[1]);
            float p3 = ex2f(S[ni][3] - mnew[1]);
            lsum[0] += p0 + p1;
            lsum[1] += p2 + p3;
            int ks = ni >> 1, half = ni & 1;
            pa[ks][half * 2 + 0] = packh2(p0, p1);
            pa[ks][half * 2 + 1] = packh2(p2, p3);
        }

        #pragma unroll
        for (int ks = 0; ks < 4; ks++) {
            #pragma unroll
            for (int nn = 0; nn < 4; nn++) {
                uint32_t vb4[4];
                int key = ks * 16 + (lane & 7) + ((lane >> 3) & 1) * 8;
                int dim = nn * 16 + ((lane >> 4) & 1) * 8;
                ldsm4t(vb4, vbase + (key * FSTR + dim) * 2);
                mma_f16(O[2 * nn],     pa[ks], &vb4[0]);
                mma_f16(O[2 * nn + 1], pa[ks], &vb4[2]);
            }
        }
    }

    #pragma unroll
    for (int j = 0; j < 2; j++) {
        lsum[j] += __shfl_xor_sync(0xffffffffu, lsum[j], 1);
        lsum[j] += __shfl_xor_sync(0xffffffffu, lsum[j], 2);
        lsum[j] = 1.0f / lsum[j];
    }
    #pragma unroll
    for (int ni = 0; ni < 8; ni++) {
        size_t grow = rowbase + q0 + wm * 16 + r4;
        int col = h * 64 + ni * 8 + 2 * c2;
        float x00 = O[ni][0] * lsum[0];
        float x01 = O[ni][1] * lsum[0];
        float x10 = O[ni][2] * lsum[1];
        float x11 = O[ni][3] * lsum[1];
        *(__half2*)(chi + grow * DMODEL + col) =
            __half2{__float2half_rn(x00), __float2half_rn(x01)};
        *(__half2*)(chi + (grow + 8) * DMODEL + col) =
            __half2{__float2half_rn(x10), __float2half_rn(x11)};
    }
}

// ---------------- launch ------------------------------------------------------
extern "C" void kernel_launch(void* const* d_in, const int* in_sizes, int n_in,
                              void* d_out, int out_size)
{
    const float* q    = (const float*)d_in[0];
    const float* k    = (const float*)d_in[1];
    const float* v    = (const float*)d_in[2];
    const void*  mask = d_in[3];
    const float* Wq   = (const float*)d_in[4];
    const float* bq   = (const float*)d_in[5];
    const float* Wk   = (const float*)d_in[6];
    const float* bk   = (const float*)d_in[7];
    const float* Wv   = (const float*)d_in[8];
    const float* bv   = (const float*)d_in[9];
    const float* Wo   = (const float*)d_in[10];
    const float* bo   = (const float*)d_in[11];

    __half *qsh, *ksh, *vsh, *qhi, *khi, *vhi, *chi, *w16;
    cudaGetSymbolAddress((void**)&qsh, g_qsh);
    cudaGetSymbolAddress((void**)&ksh, g_ksh);
    cudaGetSymbolAddress((void**)&vsh, g_vsh);
    cudaGetSymbolAddress((void**)&qhi, g_qhi);
    cudaGetSymbolAddress((void**)&khi, g_khi);
    cudaGetSymbolAddress((void**)&vhi, g_vhi);
    cudaGetSymbolAddress((void**)&chi, g_chi);
    cudaGetSymbolAddress((void**)&w16, g_w16);

    const int gemm_smem = 3 * STAGE_B;              // 61440
    const int flash_smem = (9216 + 6 * KVSTG) * 2;  // 73728
    static bool attr_set = false;
    if (!attr_set) {
        cudaFuncSetAttribute(gemm_mma, cudaFuncAttributeMaxDynamicSharedMemorySize, gemm_smem);
        cudaFuncSetAttribute(flash_mma, cudaFuncAttributeMaxDynamicSharedMemorySize, flash_smem);
        attr_set = true;
    }

    const float qscale = 0.125f * LOG2E;

    detect_mask<<<1, 256>>>((const unsigned*)mask);
    pack_mask<<<(SEQ * MWORDS) / 256, 256>>>(mask);

    conv_all<<<CONV_BLOCKS, 256>>>(
        (const float4*)q, (const float4*)k, (const float4*)v,
        (const float4*)Wq, (const float4*)Wk, (const float4*)Wv, (const float4*)Wo,
        qsh, ksh, vsh, w16);

    Jobs3 pj;
    pj.j[0] = Job{qsh, w16,                     bq, nullptr, qhi, 2, qscale};
    pj.j[1] = Job{ksh, w16 + 1 * DMODEL*DMODEL, bk, nullptr, khi, 2, 1.0f};
    pj.j[2] = Job{vsh, w16 + 2 * DMODEL*DMODEL, bv, nullptr, vhi, 2, 1.0f};
    gemm_mma<<<dim3(8, 64, 3), 128, gemm_smem>>>(pj);

    flash_mma<<<dim3(SEQ / 128, NHEAD, NBATCH), 256, flash_smem>>>(qhi, khi, vhi, chi);

    Jobs3 oj;
    oj.j[0] = Job{chi, w16 + 3 * DMODEL*DMODEL, bo, (float*)d_out, nullptr, 0, 1.0f};
    oj.j[1] = oj.j[0];
    oj.j[2] = oj.j[0];
    gemm_mma<<<dim3(8, 64, 1), 128, gemm_smem>>>(oj);
}

// round 17
// speedup vs baseline: 1.0536x; 1.0380x over previous
#include <cuda_runtime.h>
#include <cuda_fp16.h>
#include <cstdint>

#define SEQ    2048
#define DMODEL 1024
#define NHEAD  16
#define DVDIM  64
#define NBATCH 4
#define MROWS  (NBATCH * SEQ)   // 8192
#define MWORDS (SEQ / 32)
#define LOG2E  1.4426950408889634f

// ---------------- scratch (device globals) ----------------------------------
__device__ __align__(16) __half g_qsh[MROWS * DMODEL];
__device__ __align__(16) __half g_ksh[MROWS * DMODEL];
__device__ __align__(16) __half g_vsh[MROWS * DMODEL];
__device__ __align__(16) __half g_qhi[MROWS * DMODEL];
__device__ __align__(16) __half g_khi[MROWS * DMODEL];
__device__ __align__(16) __half g_vhi[MROWS * DMODEL];
__device__ __align__(16) __half g_chi[MROWS * DMODEL];
__device__ __align__(16) __half g_w16[4 * DMODEL * DMODEL];
__device__ unsigned g_mbits[SEQ * MWORDS];
__device__ int g_mode;

// ---------------- PTX helpers (sm_103-safe) ---------------------------------
__device__ __forceinline__ uint32_t smem_u32(const void* p) {
    uint32_t a;
    asm("{ .reg .u64 t; cvta.to.shared.u64 t, %1; cvt.u32.u64 %0, t; }" : "=r"(a) : "l"(p));
    return a;
}
#define CP_ASYNC16(dst, src) \
    asm volatile("cp.async.ca.shared.global [%0], [%1], 16;" :: "r"(dst), "l"(src))
#define CP_COMMIT() asm volatile("cp.async.commit_group;" ::: "memory")
#define CP_WAIT(n)  asm volatile("cp.async.wait_group %0;" :: "n"(n) : "memory")
#define STG_CS16(addr, v) \
    asm volatile("st.global.cs.v4.b32 [%0], {%1,%2,%3,%4};" \
                 :: "l"(addr), "r"((v).x), "r"((v).y), "r"((v).z), "r"((v).w) : "memory")

__device__ __forceinline__ void ldsm4(uint32_t* r, uint32_t addr) {
    asm volatile("ldmatrix.sync.aligned.m8n8.x4.shared.b16 {%0,%1,%2,%3}, [%4];"
                 : "=r"(r[0]), "=r"(r[1]), "=r"(r[2]), "=r"(r[3]) : "r"(addr));
}
__device__ __forceinline__ void ldsm4t(uint32_t* r, uint32_t addr) {
    asm volatile("ldmatrix.sync.aligned.m8n8.x4.trans.shared.b16 {%0,%1,%2,%3}, [%4];"
                 : "=r"(r[0]), "=r"(r[1]), "=r"(r[2]), "=r"(r[3]) : "r"(addr));
}
__device__ __forceinline__ void mma_f16(float* d, const uint32_t* a, const uint32_t* b) {
    asm volatile(
        "mma.sync.aligned.m16n8k16.row.col.f32.f16.f16.f32 "
        "{%0,%1,%2,%3}, {%4,%5,%6,%7}, {%8,%9}, {%0,%1,%2,%3};"
        : "+f"(d[0]), "+f"(d[1]), "+f"(d[2]), "+f"(d[3])
        : "r"(a[0]), "r"(a[1]), "r"(a[2]), "r"(a[3]), "r"(b[0]), "r"(b[1]));
}
__device__ __forceinline__ float ex2f(float x) {
    float r; asm("ex2.approx.f32 %0, %1;" : "=f"(r) : "f"(x)); return r;
}
__device__ __forceinline__ uint32_t packh2(float lo, float hi) {
    uint32_t d; asm("cvt.rn.f16x2.f32 %0, %1, %2;" : "=r"(d) : "f"(hi), "f"(lo)); return d;
}

// ---------------- mask handling ----------------------------------------------
__global__ void detect_mask(const unsigned* __restrict__ m) {
    __shared__ int f[4];
    int t = threadIdx.x;
    if (t < 4) f[t] = 0;
    __syncthreads();
    int fu8 = 0, ff16 = 0, fbf16 = 0, ff32 = 0;
    for (int i = t; i < 4096; i += 256) {
        unsigned w = m[i];
        if (w == 0x3F800000u) ff32 = 1;
        if (w == 0x3F803F80u || w == 0x00003F80u) fbf16 = 1;
        if (w == 0x3C003C00u || w == 0x00003C00u || w == 0x3C000000u) ff16 = 1;
        if ((w & 0xFEFEFEFEu) == 0u && w > 1u) fu8 = 1;
    }
    if (fu8)  atomicOr(&f[0], 1);
    if (ff16) atomicOr(&f[1], 1);
    if (fbf16) atomicOr(&f[2], 1);
    if (ff32) atomicOr(&f[3], 1);
    __syncthreads();
    if (t == 0) {
        int mode;
        if (f[1]) mode = 4;
        else if (f[2]) mode = 3;
        else if (f[3]) mode = 2;
        else if (f[0]) mode = 1;
        else mode = 0;
        g_mode = mode;
    }
}

__global__ void pack_mask(const void* __restrict__ mp) {
    int idx = blockIdx.x * blockDim.x + threadIdx.x;
    int mode = g_mode;
    long base = (long)idx * 32;
    unsigned bits = 0;
    if (mode == 0) {
        const int* p = (const int*)mp;
        #pragma unroll 8
        for (int j = 0; j < 32; j++) if (p[base + j] != 0) bits |= 1u << j;
    } else if (mode == 1) {
        const unsigned char* p = (const unsigned char*)mp;
        #pragma unroll 8
        for (int j = 0; j < 32; j++) if (p[base + j] != 0) bits |= 1u << j;
    } else if (mode == 2) {
        const float* p = (const float*)mp;
        #pragma unroll 8
        for (int j = 0; j < 32; j++) if (p[base + j] != 0.0f) bits |= 1u << j;
    } else {
        const unsigned short* p = (const unsigned short*)mp;
        #pragma unroll 8
        for (int j = 0; j < 32; j++) if (p[base + j] != 0) bits |= 1u << j;
    }
    g_mbits[idx] = bits;
}

// ---------------- prep: conversions, flat exact grid -------------------------
#define CONV_BLOCKS 7168

__global__ void __launch_bounds__(256) conv_all(
    const float4* __restrict__ q, const float4* __restrict__ k,
    const float4* __restrict__ v,
    const float4* __restrict__ wq, const float4* __restrict__ wk,
    const float4* __restrict__ wv, const float4* __restrict__ wo,
    __half* __restrict__ qh, __half* __restrict__ kh,
    __half* __restrict__ vh, __half* __restrict__ w16)
{
    int blk = blockIdx.x;
    const float4* src;
    __half* dst;
    int i;
    if (blk < 6144) {
        int z = blk >> 11;
        i = (blk & 2047) * 256 + threadIdx.x;
        src = (z == 0) ? q : (z == 1) ? k : v;
        dst = (z == 0) ? qh : (z == 1) ? kh : vh;
    } else {
        int w = (blk - 6144) >> 8;
        i = ((blk - 6144) & 255) * 256 + threadIdx.x;
        src = (w == 0) ? wq : (w == 1) ? wk : (w == 2) ? wv : wo;
        dst = w16 + (size_t)w * DMODEL * DMODEL;
    }
    float4 a = src[4 * i], b = src[4 * i + 1];
    float4 c = src[4 * i + 2], d = src[4 * i + 3];
    uint4 o0, o1;
    o0.x = packh2(a.x, a.y); o0.y = packh2(a.z, a.w);
    o0.z = packh2(b.x, b.y); o0.w = packh2(b.z, b.w);
    o1.x = packh2(c.x, c.y); o1.y = packh2(c.z, c.w);
    o1.z = packh2(d.x, d.y); o1.w = packh2(d.z, d.w);
    uint4* op = (uint4*)dst + 2 * i;
    STG_CS16(op, o0);
    STG_CS16(op + 1, o1);
}

// ---------------- mma.sync fp16 GEMM (at HMMA floor) --------------------------
#define LDA_B   80
#define TILE_B  10240
#define STAGE_B 20480
#define NITER   (DMODEL / 32)

struct Job {
    const __half* A1; const __half* B1;
    const float* bias;
    float* Yf; __half* H1;
    int mode; float scale;
};
struct Jobs3 { Job j[3]; };

__global__ void __launch_bounds__(128) gemm_mma(Jobs3 jobs)
{
    extern __shared__ char sm[];
    uint32_t smb = smem_u32(sm);
    Job jb = jobs.j[blockIdx.z];
    int tid = threadIdx.x, lane = tid & 31, wid = tid >> 5;
    int wm = wid >> 1, wn = wid & 1;
    int m0 = blockIdx.y * 128, n0 = blockIdx.x * 128;

    float acc[4][8][4];
    #pragma unroll
    for (int i = 0; i < 4; i++)
        #pragma unroll
        for (int j = 0; j < 8; j++)
            #pragma unroll
            for (int q = 0; q < 4; q++) acc[i][j][q] = 0.0f;

    const __half* A1p = jb.A1; const __half* B1p = jb.B1;

    auto issue = [&](int t) {
        uint32_t st = smb + (t % 3) * STAGE_B;
        int k0 = t * 32;
        #pragma unroll
        for (int i = 0; i < 4; i++) {
            int idx = tid + i * 128;
            int r = idx >> 2, c = idx & 3;
            uint32_t d = st + r * LDA_B + c * 16;
            size_t ga = (size_t)(m0 + r) * DMODEL + k0 + c * 8;
            size_t gb = (size_t)(n0 + r) * DMODEL + k0 + c * 8;
            CP_ASYNC16(d,          A1p + ga);
            CP_ASYNC16(d + TILE_B, B1p + gb);
        }
        CP_COMMIT();
    };
    issue(0);
    issue(1);

    for (int t = 0; t < NITER; t++) {
        if (t + 1 < NITER) { CP_WAIT(1); } else { CP_WAIT(0); }
        __syncthreads();
        if (t + 2 < NITER) issue(t + 2);

        uint32_t st = smb + (t % 3) * STAGE_B;
        uint32_t aA = st + (wm * 64 + (lane & 15)) * LDA_B + (lane >> 4) * 16;
        uint32_t aB = st + TILE_B + (wn * 64 + (lane & 7)) * LDA_B + (lane >> 3) * 16;

        uint32_t bh[8][4];
        #pragma unroll
        for (int ni = 0; ni < 8; ni++) ldsm4(bh[ni], aB + ni * 8 * LDA_B);

        #pragma unroll
        for (int ks = 0; ks < 2; ks++) {
            uint32_t ah[4][4];
            #pragma unroll
            for (int mi = 0; mi < 4; mi++)
                ldsm4(ah[mi], aA + mi * 16 * LDA_B + ks * 32);
            #pragma unroll
            for (int mi = 0; mi < 4; mi++)
                #pragma unroll
                for (int ni = 0; ni < 8; ni++)
                    mma_f16(acc[mi][ni], ah[mi], &bh[ni][2 * ks]);
        }
    }

    int er = lane >> 2, ec = (lane & 3) * 2;
    #pragma unroll
    for (int mi = 0; mi < 4; mi++) {
        #pragma unroll
        for (int ni = 0; ni < 8; ni++) {
            int row = m0 + wm * 64 + mi * 16 + er;
            int col = n0 + wn * 64 + ni * 8 + ec;
            float b0 = jb.bias[col], b1 = jb.bias[col + 1];
            float x00 = acc[mi][ni][0] + b0, x01 = acc[mi][ni][1] + b1;
            float x10 = acc[mi][ni][2] + b0, x11 = acc[mi][ni][3] + b1;
            if (jb.mode == 0) {
                *(float2*)(jb.Yf + (size_t)row * DMODEL + col) = float2{x00, x01};
                *(float2*)(jb.Yf + (size_t)(row + 8) * DMODEL + col) = float2{x10, x11};
            } else {
                x00 *= jb.scale; x01 *= jb.scale; x10 *= jb.scale; x11 *= jb.scale;
                *(__half2*)(jb.H1 + (size_t)row * DMODEL + col) =
                    __half2{__float2half_rn(x00), __float2half_rn(x01)};
                *(__half2*)(jb.H1 + (size_t)(row + 8) * DMODEL + col) =
                    __half2{__float2half_rn(x10), __float2half_rn(x11)};
            }
        }
    }
}

// ---------------- fused MMA flash attention -----------------------------------
#define FSTR 72
#define MASKVAL 1.4426950409e-9f
#define KVSTG 4608
#define NT (SEQ / 64)

__global__ void __launch_bounds__(256, 2) flash_mma(
    const __half* __restrict__ qhi, const __half* __restrict__ khi,
    const __half* __restrict__ vhi, __half* __restrict__ chi)
{
    extern __shared__ __half sh[];
    const int O_QHI = 0;
    const int O_KH0 = 9216;
    const int O_V0  = 9216 + 3 * KVSTG;
    uint32_t sb = smem_u32(sh);

    int tid = threadIdx.x, lane = tid & 31, wm = tid >> 5;
    int q0 = blockIdx.x * 128, h = blockIdx.y, b = blockIdx.z;
    size_t rowbase = (size_t)b * SEQ;
    int r4 = lane >> 2, c2 = lane & 3;

    {
        const __half* qh = qhi + (rowbase + q0) * DMODEL + h * 64;
        #pragma unroll
        for (int c = tid; c < 1024; c += 256) {
            int r = c >> 3, dc = c & 7;
            CP_ASYNC16(sb + (O_QHI + r * FSTR + dc * 8) * 2, qh + (size_t)r * DMODEL + dc * 8);
        }
        CP_COMMIT();
    }
    const __half* kbh = khi + rowbase * DMODEL + h * 64;
    const __half* vb  = vhi + rowbase * DMODEL + h * 64;

    auto issue_kv = [&](int t) {
        int st = t % 3;
        int k0 = t * 64;
        #pragma unroll
        for (int c = tid; c < 512; c += 256) {
            int r = c >> 3, dc = c & 7;
            size_t g = (size_t)(k0 + r) * DMODEL + dc * 8;
            CP_ASYNC16(sb + (O_KH0 + st * KVSTG + r * FSTR + dc * 8) * 2, kbh + g);
            CP_ASYNC16(sb + (O_V0  + st * KVSTG + r * FSTR + dc * 8) * 2, vb + g);
        }
        CP_COMMIT();
    };
    issue_kv(0);
    issue_kv(1);

    float O[8][4];
    #pragma unroll
    for (int ni = 0; ni < 8; ni++)
        #pragma unroll
        for (int q = 0; q < 4; q++) O[ni][q] = 0.0f;
    float lsum[2] = {0.f, 0.f};
    float mrow[2] = {-1e30f, -1e30f};

    for (int t = 0; t < NT; t++) {
        if (t + 2 < NT) { CP_WAIT(1); } else { CP_WAIT(0); }
        __syncthreads();
        if (t + 2 < NT) issue_kv(t + 2);

        int st = t % 3;
        uint32_t kbase = sb + (O_KH0 + st * KVSTG) * 2;
        uint32_t vbase = sb + (O_V0  + st * KVSTG) * 2;

        uint2 mw[2];
        #pragma unroll
        for (int rr = 0; rr < 2; rr++) {
            int grow = q0 + wm * 16 + r4 + rr * 8;
            mw[rr] = __ldg((const uint2*)&g_mbits[(size_t)grow * MWORDS + 2 * t]);
        }

        float S[8][4];
        #pragma unroll
        for (int ni = 0; ni < 8; ni++)
            #pragma unroll
            for (int q = 0; q < 4; q++) S[ni][q] = 0.0f;

        #pragma unroll
        for (int ks = 0; ks < 4; ks++) {
            uint32_t aH[4];
            {
                uint32_t abase = sb + (((wm * 16 + (lane & 15)) * FSTR) +
                                       (lane >> 4) * 8 + ks * 16) * 2;
                ldsm4(aH, abase);
            }
            uint32_t bH[8][2];
            #pragma unroll
            for (int np = 0; np < 4; np++) {
                uint32_t r4v[4];
                uint32_t boff = ((np * 16 + (lane & 7) + ((lane >> 4) & 1) * 8) * FSTR +
                                 ks * 16 + ((lane >> 3) & 1) * 8) * 2;
                ldsm4(r4v, kbase + boff);
                bH[2 * np][0] = r4v[0];     bH[2 * np][1] = r4v[1];
                bH[2 * np + 1][0] = r4v[2]; bH[2 * np + 1][1] = r4v[3];
            }
            #pragma unroll
            for (int ni = 0; ni < 8; ni++)
                mma_f16(S[ni], aH, bH[ni]);
        }

        float mnew[2] = {mrow[0], mrow[1]};
        #pragma unroll
        for (int ni = 0; ni < 8; ni++) {
            uint32_t w0 = (ni < 4) ? mw[0].x : mw[0].y;
            uint32_t w1 = (ni < 4) ? mw[1].x : mw[1].y;
            int shf = (ni & 3) * 8 + 2 * c2;
            if ((w0 >> shf) & 1u)       S[ni][0] = MASKVAL;
            if ((w0 >> (shf + 1)) & 1u) S[ni][1] = MASKVAL;
            if ((w1 >> shf) & 1u)       S[ni][2] = MASKVAL;
            if ((w1 >> (shf + 1)) & 1u) S[ni][3] = MASKVAL;
            mnew[0] = fmaxf(mnew[0], fmaxf(S[ni][0], S[ni][1]));
            mnew[1] = fmaxf(mnew[1], fmaxf(S[ni][2], S[ni][3]));
        }
        #pragma unroll
        for (int j = 0; j < 2; j++) {
            mnew[j] = fmaxf(mnew[j], __shfl_xor_sync(0xffffffffu, mnew[j], 1));
            mnew[j] = fmaxf(mnew[j], __shfl_xor_sync(0xffffffffu, mnew[j], 2));
        }
        float al[2];
        #pragma unroll
        for (int j = 0; j < 2; j++) {
            al[j] = ex2f(mrow[j] - mnew[j]);
            mrow[j] = mnew[j];
            lsum[j] *= al[j];
        }
        #pragma unroll
        for (int ni = 0; ni < 8; ni++) {
            O[ni][0] *= al[0]; O[ni][1] *= al[0];
            O[ni][2] *= al[1]; O[ni][3] *= al[1];
        }

        uint32_t pa[4][4];
        #pragma unroll
        for (int ni = 0; ni < 8; ni++) {
            float p0 = ex2f(S[ni][0] - mnew[0]);
            float p1 = ex2f(S[ni][1] - mnew[0]);
            float p2 = ex2f(S[ni][2] - mnew[1]);
            float p3 = ex2f(S[ni][3] - mnew[1]);
            lsum[0] += p0 + p1;
            lsum[1] += p2 + p3;
            int ks = ni >> 1, half = ni & 1;
            pa[ks][half * 2 + 0] = packh2(p0, p1);
            pa[ks][half * 2 + 1] = packh2(p2, p3);
        }

        #pragma unroll
        for (int ks = 0; ks < 4; ks++) {
            #pragma unroll
            for (int nn = 0; nn < 4; nn++) {
                uint32_t vb4[4];
                int key = ks * 16 + (lane & 7) + ((lane >> 3) & 1) * 8;
                int dim = nn * 16 + ((lane >> 4) & 1) * 8;
                ldsm4t(vb4, vbase + (key * FSTR + dim) * 2);
                mma_f16(O[2 * nn],     pa[ks], &vb4[0]);
                mma_f16(O[2 * nn + 1], pa[ks], &vb4[2]);
            }
        }
    }

    #pragma unroll
    for (int j = 0; j < 2; j++) {
        lsum[j] += __shfl_xor_sync(0xffffffffu, lsum[j], 1);
        lsum[j] += __shfl_xor_sync(0xffffffffu, lsum[j], 2);
        lsum[j] = 1.0f / lsum[j];
    }
    #pragma unroll
    for (int ni = 0; ni < 8; ni++) {
        size_t grow = rowbase + q0 + wm * 16 + r4;
        int col = h * 64 + ni * 8 + 2 * c2;
        float x00 = O[ni][0] * lsum[0];
        float x01 = O[ni][1] * lsum[0];
        float x10 = O[ni][2] * lsum[1];
        float x11 = O[ni][3] * lsum[1];
        *(__half2*)(chi + grow * DMODEL + col) =
            __half2{__float2half_rn(x00), __float2half_rn(x01)};
        *(__half2*)(chi + (grow + 8) * DMODEL + col) =
            __half2{__float2half_rn(x10), __float2half_rn(x11)};
    }
}

// ---------------- launch ------------------------------------------------------
extern "C" void kernel_launch(void* const* d_in, const int* in_sizes, int n_in,
                              void* d_out, int out_size)
{
    const float* q    = (const float*)d_in[0];
    const float* k    = (const float*)d_in[1];
    const float* v    = (const float*)d_in[2];
    const void*  mask = d_in[3];
    const float* Wq   = (const float*)d_in[4];
    const float* bq   = (const float*)d_in[5];
    const float* Wk   = (const float*)d_in[6];
    const float* bk   = (const float*)d_in[7];
    const float* Wv   = (const float*)d_in[8];
    const float* bv   = (const float*)d_in[9];
    const float* Wo   = (const float*)d_in[10];
    const float* bo   = (const float*)d_in[11];

    __half *qsh, *ksh, *vsh, *qhi, *khi, *vhi, *chi, *w16;
    cudaGetSymbolAddress((void**)&qsh, g_qsh);
    cudaGetSymbolAddress((void**)&ksh, g_ksh);
    cudaGetSymbolAddress((void**)&vsh, g_vsh);
    cudaGetSymbolAddress((void**)&qhi, g_qhi);
    cudaGetSymbolAddress((void**)&khi, g_khi);
    cudaGetSymbolAddress((void**)&vhi, g_vhi);
    cudaGetSymbolAddress((void**)&chi, g_chi);
    cudaGetSymbolAddress((void**)&w16, g_w16);

    const int gemm_smem = 3 * STAGE_B;              // 61440
    const int flash_smem = (9216 + 6 * KVSTG) * 2;  // 73728
    static bool init_done = false;
    static cudaStream_t s2;
    static cudaEvent_t evFork, evJoin;
    if (!init_done) {
        cudaFuncSetAttribute(gemm_mma, cudaFuncAttributeMaxDynamicSharedMemorySize, gemm_smem);
        cudaFuncSetAttribute(flash_mma, cudaFuncAttributeMaxDynamicSharedMemorySize, flash_smem);
        cudaStreamCreateWithFlags(&s2, cudaStreamNonBlocking);
        cudaEventCreateWithFlags(&evFork, cudaEventDisableTiming);
        cudaEventCreateWithFlags(&evJoin, cudaEventDisableTiming);
        init_done = true;
    }

    const float qscale = 0.125f * LOG2E;

    // fork: mask chain on s2 runs concurrently with conv + proj GEMM
    cudaEventRecord(evFork, 0);
    cudaStreamWaitEvent(s2, evFork, 0);
    detect_mask<<<1, 256, 0, s2>>>((const unsigned*)mask);
    pack_mask<<<(SEQ * MWORDS) / 256, 256, 0, s2>>>(mask);
    cudaEventRecord(evJoin, s2);

    conv_all<<<CONV_BLOCKS, 256>>>(
        (const float4*)q, (const float4*)k, (const float4*)v,
        (const float4*)Wq, (const float4*)Wk, (const float4*)Wv, (const float4*)Wo,
        qsh, ksh, vsh, w16);

    Jobs3 pj;
    pj.j[0] = Job{qsh, w16,                     bq, nullptr, qhi, 2, qscale};
    pj.j[1] = Job{ksh, w16 + 1 * DMODEL*DMODEL, bk, nullptr, khi, 2, 1.0f};
    pj.j[2] = Job{vsh, w16 + 2 * DMODEL*DMODEL, bv, nullptr, vhi, 2, 1.0f};
    gemm_mma<<<dim3(8, 64, 3), 128, gemm_smem>>>(pj);

    // join: flash needs the packed mask
    cudaStreamWaitEvent(0, evJoin, 0);
    flash_mma<<<dim3(SEQ / 128, NHEAD, NBATCH), 256, flash_smem>>>(qhi, khi, vhi, chi);

    Jobs3 oj;
    oj.j[0] = Job{chi, w16 + 3 * DMODEL*DMODEL, bo, (float*)d_out, nullptr, 0, 1.0f};
    oj.j[1] = oj.j[0];
    oj.j[2] = oj.j[0];
    gemm_mma<<<dim3(8, 64, 1), 128, gemm_smem>>>(oj);
}